// round 10
// baseline (speedup 1.0000x reference)
#include <cuda_runtime.h>
#include <cuda_bf16.h>
#include <cstdint>

#define BB   64
#define NN   2048
#define SS   512
#define NCTA 64
#define TPB  256
#define CPC  32          // columns per CTA
#define KBLK 256
#define NKB  (NN/KBLK)   // 8
#define PIPE 3
#define ROWB 512                 // bytes per tile row (256 k-elems bf16)
#define A_STG (BB*ROWB)          // 32768
#define W_STG (CPC*ROWB)         // 16384
#define W_TOT (NKB*W_STG)        // 131072 (persistent in smem)
#define DSM_BYTES (W_TOT + PIPE*A_STG)   // 229376
#define NGRP 8                   // producer groups (8 CTAs each -> one K-stage)

// Global scratch (pre-swizzled tiled layouts; chunk16 index XOR (row&7))
__device__ __align__(128) unsigned char g_W2[(size_t)NCTA * W_TOT];   // 8MB
__device__ __align__(128) unsigned char g_e2[2][NKB * A_STG];         // 2x256KB
__device__ float g_Sf[NCTA][BB];     // final-step partials only
__device__ unsigned g_done[NGRP];    // per-group step counters

// ---- setup: W_rec -> g_W2 (bf16 tiled+swizzled); h0 -> g_e2[1]; reset counters ----
__global__ void k_setup(const float* __restrict__ W, const float* __restrict__ h0) {
    const int tid = threadIdx.x;
    if (blockIdx.y < NKB) {
        __shared__ float s[256][33];
        const int cta = blockIdx.x, kb = blockIdx.y;
        const int n0 = cta * 32, k0 = kb * 256;
        for (int idx = tid; idx < 256 * 32; idx += TPB) {
            int k = idx >> 5, nl = idx & 31;
            s[k][nl] = W[(size_t)(k0 + k) * NN + n0 + nl];
        }
        __syncthreads();
        unsigned char* dst = g_W2 + (size_t)cta * W_TOT + (size_t)kb * W_STG;
        for (int it = tid; it < 32 * 32; it += TPB) {
            int rl = it >> 5, ch = it & 31;
            __nv_bfloat16 v[8];
#pragma unroll
            for (int j = 0; j < 8; j++) v[j] = __float2bfloat16(s[ch * 8 + j][rl]);
            *(uint4*)(dst + rl * ROWB + ((ch ^ (rl & 7)) << 4)) = *(uint4*)v;
        }
    } else {
        int item = blockIdx.x * TPB + tid;         // 64*256 = BB*NN/8
        {
            int b = item >> 8, ch = item & 255;
            __nv_bfloat16 v[8];
            const float* src = h0 + (size_t)b * NN + ch * 8;
#pragma unroll
            for (int j = 0; j < 8; j++) v[j] = __float2bfloat16(src[j]);
            int kb = ch >> 5, chl = ch & 31;
            unsigned char* dst = g_e2[1] + (size_t)kb * A_STG + b * ROWB + ((chl ^ (b & 7)) << 4);
            *(uint4*)dst = *(uint4*)v;
        }
        if (item < NGRP) g_done[item] = 0u;
    }
}

__device__ __forceinline__ void mbar_init(unsigned mb, unsigned cnt) {
    asm volatile("mbarrier.init.shared.b64 [%0], %1;" :: "r"(mb), "r"(cnt) : "memory");
}
__device__ __forceinline__ void mbar_expect(unsigned mb, unsigned bytes) {
    asm volatile("mbarrier.arrive.expect_tx.shared.b64 _, [%0], %1;" :: "r"(mb), "r"(bytes) : "memory");
}
__device__ __forceinline__ void bulk_ld(unsigned dst, const void* src, unsigned bytes, unsigned mb) {
    asm volatile("cp.async.bulk.shared::cluster.global.mbarrier::complete_tx::bytes [%0], [%1], %2, [%3];"
                 :: "r"(dst), "l"(src), "r"(bytes), "r"(mb) : "memory");
}
__device__ __forceinline__ void mbar_wait(unsigned mb, unsigned ph) {
    asm volatile("{\n\t.reg .pred P;\n"
                 "W0_%=:\n\t"
                 "mbarrier.try_wait.parity.acquire.cta.shared::cta.b64 P, [%0], %1, 0x989680;\n\t"
                 "@P bra W1_%=;\n\t"
                 "bra W0_%=;\n"
                 "W1_%=:\n\t}"
                 :: "r"(mb), "r"(ph) : "memory");
}
__device__ __forceinline__ void signal_group() {
    asm volatile("red.release.gpu.global.add.u32 [%0], %1;"
                 :: "l"(&g_done[blockIdx.x >> 3]), "r"(1u) : "memory");
}
__device__ __forceinline__ void poll_ge(const unsigned* p, unsigned thr) {
    unsigned v;
    do {
        asm volatile("ld.acquire.gpu.u32 %0, [%1];" : "=r"(v) : "l"(p) : "memory");
    } while (v < thr);
}

extern __shared__ __align__(128) unsigned char dsm[];  // [W 128KB][A 3x32KB]

__global__ void __launch_bounds__(TPB, 1) k_step(
    const float* __restrict__ vel, const float* __restrict__ Wlin,
    const float* __restrict__ blin, float* __restrict__ out)
{
    __shared__ float sV0[BB], sV1[BB], sCur[BB], sWp[2][BB];
    __shared__ __align__(8) unsigned long long mbar[PIPE + 1];   // [0..2]=A stages, [3]=W

    const int tid = threadIdx.x;
    const int w = tid >> 5, l = tid & 31;
    const int g = l >> 2, tg = l & 3;
    const int mrow0 = (w & 3) * 16;
    const int nloc0 = (w >> 2) * 16;
    const int ccol0 = blockIdx.x * CPC;
    const int r0 = mrow0 + g, r1 = r0 + 8;

    const unsigned smemW = (unsigned)__cvta_generic_to_shared(dsm);
    const unsigned smemA = smemW + W_TOT;
    unsigned mb[PIPE + 1];
#pragma unroll
    for (int p = 0; p < PIPE + 1; p++) mb[p] = (unsigned)__cvta_generic_to_shared(&mbar[p]);
    if (tid == 0) {
#pragma unroll
        for (int p = 0; p < PIPE + 1; p++) mbar_init(mb[p], 1u);
    }
    __syncthreads();

    // load persistent W slice (128KB) once
    if (tid == 0) {
        mbar_expect(mb[PIPE], W_TOT);
        bulk_ld(smemW, g_W2 + (size_t)blockIdx.x * W_TOT, W_TOT, mb[PIPE]);
    }

    // per-thread output columns + linear-layer constants
    float wl0[4], wl1[4], bl4[4]; int ncg[4];
#pragma unroll
    for (int j = 0; j < 2; j++)
#pragma unroll
        for (int q = 0; q < 2; q++) {
            int idx = j * 2 + q;
            int n = ccol0 + nloc0 + j * 8 + tg * 2 + q;
            ncg[idx] = n; wl0[idx] = Wlin[n * 2]; wl1[idx] = Wlin[n * 2 + 1]; bl4[idx] = blin[n];
        }

    // ldmatrix per-lane row bases + swizzle params
    const int rowA = mrow0 + (l & 15);
    const int mA = rowA & 7, halfA = (l >> 4) & 1;
    const unsigned aRow = smemA + rowA * ROWB;
    const int bq = l >> 3;
    const int rowB = nloc0 + ((bq & 2) ? 8 : 0) + (l & 7);
    const int mB = rowB & 7, halfB = bq & 1;
    const unsigned bRow = smemW + rowB * ROWB;

    // constant ones-column B fragment (col 0 = 1.0, cols 1-7 = 0)
    const unsigned bAux = ((l >> 2) == 0) ? 0x3F803F80u : 0u;

    float acc[2][4];
#pragma unroll
    for (int j = 0; j < 2; j++)
#pragma unroll
        for (int q = 0; q < 4; q++) acc[j][q] = 0.f;
    float accS0 = 0.f, accS2 = 0.f;   // row-sum accumulators (c0=r0, c2=r1)
    float ek[8];

    mbar_wait(mb[PIPE], 0u);   // W ready
    __syncthreads();

    for (int t = 0; t < SS; t++) {
        const unsigned ut = (unsigned)t;
        const unsigned char* eBuf = g_e2[(t + 1) & 1];

        // lanes 0-7: poll producer-group counters; lanes 0-2 issue prologue TMA ASAP
        if (tid < NGRP) {
            poll_ge(&g_done[tid], 8u * ut);
            if (tid < PIPE) {
                unsigned A = 8u * ut + (unsigned)tid;
                unsigned slot = A % 3u;
                mbar_expect(mb[slot], A_STG);
                bulk_ld(smemA + slot * A_STG, eBuf + (size_t)tid * A_STG, A_STG, mb[slot]);
            }
        }
        // lanes 64-127: stage velocities
        if (tid >= 64 && tid < 128) {
            int vb = tid - 64;
            float2 v = *(const float2*)&vel[((size_t)vb * SS + t) * 2];
            sV0[vb] = v.x; sV1[vb] = v.y;
        }
        __syncthreads();   // barrier: all 8 groups >= 8t, prologue TMA in flight

        // ---- GEMM: 8 K-stages; A via 3-stage TMA pipeline, W persistent ----
#pragma unroll 1
        for (int kb = 0; kb < NKB; kb++) {
            const unsigned A = 8u * ut + (unsigned)kb;
            const unsigned slot = A % 3u;
            const unsigned ph = (A / 3u) & 1u;
            mbar_wait(mb[slot], ph);
            const unsigned aB = aRow + slot * A_STG;
            const unsigned bB = bRow + kb * W_STG;
#pragma unroll
            for (int kkIdx = 0; kkIdx < KBLK / 16; kkIdx++) {
                unsigned a0, a1, a2, a3, b0, b1, b2, b3;
                unsigned aA = aB + ((unsigned)((kkIdx * 2 + halfA) ^ mA) << 4);
                unsigned bA = bB + ((unsigned)((kkIdx * 2 + halfB) ^ mB) << 4);
                asm volatile("ldmatrix.sync.aligned.m8n8.x4.shared.b16 {%0,%1,%2,%3},[%4];"
                             : "=r"(a0), "=r"(a1), "=r"(a2), "=r"(a3) : "r"(aA));
                asm volatile("ldmatrix.sync.aligned.m8n8.x4.shared.b16 {%0,%1,%2,%3},[%4];"
                             : "=r"(b0), "=r"(b1), "=r"(b2), "=r"(b3) : "r"(bA));
                asm volatile("mma.sync.aligned.m16n8k16.row.col.f32.bf16.bf16.f32 "
                             "{%0,%1,%2,%3},{%4,%5,%6,%7},{%8,%9},{%0,%1,%2,%3};"
                             : "+f"(acc[0][0]), "+f"(acc[0][1]), "+f"(acc[0][2]), "+f"(acc[0][3])
                             : "r"(a0), "r"(a1), "r"(a2), "r"(a3), "r"(b0), "r"(b1));
                asm volatile("mma.sync.aligned.m16n8k16.row.col.f32.bf16.bf16.f32 "
                             "{%0,%1,%2,%3},{%4,%5,%6,%7},{%8,%9},{%0,%1,%2,%3};"
                             : "+f"(acc[1][0]), "+f"(acc[1][1]), "+f"(acc[1][2]), "+f"(acc[1][3])
                             : "r"(a0), "r"(a1), "r"(a2), "r"(a3), "r"(b2), "r"(b3));
                if (w < 4) {   // ones-column MMA: accumulates row sums of A
                    float d1, d3;  // dummies (cols 1 region)
                    asm volatile("mma.sync.aligned.m16n8k16.row.col.f32.bf16.bf16.f32 "
                                 "{%0,%1,%2,%3},{%4,%5,%6,%7},{%8,%9},{%0,%1,%2,%3};"
                                 : "+f"(accS0), "+f"(d1), "+f"(accS2), "+f"(d3)
                                 : "r"(a0), "r"(a1), "r"(a2), "r"(a3), "r"(bAux), "r"(bAux));
                }
            }
            __syncthreads();   // all warps done with this A slot
            if (kb + PIPE < NKB && tid == 0) {
                unsigned A2 = A + PIPE;
                unsigned slot2 = A2 % 3u;          // == slot (just freed)
                mbar_expect(mb[slot2], A_STG);
                bulk_ld(smemA + slot2 * A_STG, eBuf + (size_t)(kb + PIPE) * A_STG, A_STG, mb[slot2]);
            }
        }

        // ---- epilogue ----
        if (w < 4 && tg == 0) { sCur[r0] = accS0; sCur[r1] = accS2; }
        __syncthreads();
        const float is0 = (t == 0) ? 1.f : 1.f / sCur[r0];
        const float is1 = (t == 0) ? 1.f : 1.f / sCur[r1];

        // write h_{t-1} = e_{t-1} / s_{t-1} (ek holds e_{t-1}, is = 1/s_{t-1})
        if (t > 0) {
#pragma unroll
            for (int j = 0; j < 2; j++) {
                *(float2*)&out[((size_t)r0 * SS + (t - 1)) * NN + ncg[j * 2]] =
                    make_float2(ek[j * 2] * is0, ek[j * 2 + 1] * is0);
                *(float2*)&out[((size_t)r1 * SS + (t - 1)) * NN + ncg[j * 2]] =
                    make_float2(ek[4 + j * 2] * is1, ek[4 + j * 2 + 1] * is1);
            }
        }

        // z = lin + zrec/s_{t-1} ; e_t = exp(z)
#pragma unroll
        for (int j = 0; j < 2; j++)
#pragma unroll
            for (int q = 0; q < 2; q++) {
                int idx = j * 2 + q;
                float lin0 = fmaf(sV0[r0], wl0[idx], fmaf(sV1[r0], wl1[idx], bl4[idx]));
                float lin1 = fmaf(sV0[r1], wl0[idx], fmaf(sV1[r1], wl1[idx], bl4[idx]));
                float e0 = __expf(fmaf(acc[j][q],     is0, lin0));
                float e1 = __expf(fmaf(acc[j][2 + q], is1, lin1));
                ek[idx] = e0; ek[4 + idx] = e1;
                acc[j][q] = 0.f; acc[j][2 + q] = 0.f;
            }
        accS0 = 0.f; accS2 = 0.f;

        // store e_t into tiled+swizzled layout for next step's bulk loads
        unsigned char* ecur = g_e2[t & 1];
#pragma unroll
        for (int j = 0; j < 2; j++) {
            int n = ncg[j * 2];
            int kb2 = n >> 8, cb = (n & 255) * 2;
            unsigned sw0 = (unsigned)(((cb >> 4) ^ (r0 & 7)) << 4) | (cb & 15);
            unsigned sw1 = (unsigned)(((cb >> 4) ^ (r1 & 7)) << 4) | (cb & 15);
            *(__nv_bfloat162*)(ecur + (size_t)kb2 * A_STG + r0 * ROWB + sw0) =
                __floats2bfloat162_rn(ek[j * 2], ek[j * 2 + 1]);
            *(__nv_bfloat162*)(ecur + (size_t)kb2 * A_STG + r1 * ROWB + sw1) =
                __floats2bfloat162_rn(ek[4 + j * 2], ek[4 + j * 2 + 1]);
        }
        __syncthreads();           // all e stores issued before signal
        if (tid == 0) signal_group();
    }

    // ---- final: s_{511} via one-time cross-CTA reduction, write h_{511} ----
    {
        float se0 = ek[0] + ek[1] + ek[2] + ek[3];
        float se1 = ek[4] + ek[5] + ek[6] + ek[7];
        se0 += __shfl_xor_sync(0xffffffffu, se0, 1); se0 += __shfl_xor_sync(0xffffffffu, se0, 2);
        se1 += __shfl_xor_sync(0xffffffffu, se1, 1); se1 += __shfl_xor_sync(0xffffffffu, se1, 2);
        if (tg == 0) { sWp[w >> 2][r0] = se0; sWp[w >> 2][r1] = se1; }
        __syncthreads();
        if (tid < BB) {
            float s = sWp[0][tid] + sWp[1][tid];
            asm volatile("st.release.gpu.f32 [%0], %1;" :: "l"(&g_Sf[blockIdx.x][tid]), "f"(s) : "memory");
        }
        __syncthreads();
        if (tid == 0) signal_group();
        if (tid < NGRP) poll_ge(&g_done[tid], 8u * (unsigned)(SS + 1));
        __syncthreads();
        if (tid < BB) {
            const float* pp = &g_Sf[0][0] + tid;
            float a0=0,a1=0,a2=0,a3=0,a4=0,a5=0,a6=0,a7=0;
#pragma unroll
            for (int c = 0; c < NCTA; c += 8) {
                a0 += __ldcg(pp + (c+0)*BB); a1 += __ldcg(pp + (c+1)*BB);
                a2 += __ldcg(pp + (c+2)*BB); a3 += __ldcg(pp + (c+3)*BB);
                a4 += __ldcg(pp + (c+4)*BB); a5 += __ldcg(pp + (c+5)*BB);
                a6 += __ldcg(pp + (c+6)*BB); a7 += __ldcg(pp + (c+7)*BB);
            }
            sCur[tid] = (((a0+a1)+(a2+a3)) + ((a4+a5)+(a6+a7)));
        }
        __syncthreads();
        const float is0 = 1.f / sCur[r0], is1 = 1.f / sCur[r1];
#pragma unroll
        for (int j = 0; j < 2; j++) {
            *(float2*)&out[((size_t)r0 * SS + (SS - 1)) * NN + ncg[j * 2]] =
                make_float2(ek[j * 2] * is0, ek[j * 2 + 1] * is0);
            *(float2*)&out[((size_t)r1 * SS + (SS - 1)) * NN + ncg[j * 2]] =
                make_float2(ek[4 + j * 2] * is1, ek[4 + j * 2 + 1] * is1);
        }
    }
}

extern "C" void kernel_launch(void* const* d_in, const int* in_sizes, int n_in,
                              void* d_out, int out_size) {
    const float* vel  = (const float*)d_in[0];
    const float* h0   = (const float*)d_in[1];
    const float* Wlin = (const float*)d_in[2];
    const float* blin = (const float*)d_in[3];
    const float* Wrec = (const float*)d_in[4];
    float* out = (float*)d_out;
    static int configured = 0;
    if (!configured) {
        cudaFuncSetAttribute(k_step, cudaFuncAttributeMaxDynamicSharedMemorySize, DSM_BYTES);
        configured = 1;
    }
    k_setup<<<dim3(NCTA, NKB + 1), TPB>>>(Wrec, h0);
    k_step<<<NCTA, TPB, DSM_BYTES>>>(vel, Wlin, blin, out);
}

// round 16
// speedup vs baseline: 1.1386x; 1.1386x over previous
#include <cuda_runtime.h>
#include <cuda_bf16.h>
#include <cstdint>

#define BB   64
#define NN   2048
#define SS   512
#define NCTA 64
#define TPB  256
#define CPC  32          // columns per CTA
#define KBLK 256
#define NKB  (NN/KBLK)   // 8
#define PIPE 3
#define ROWB 512                 // bytes per tile row (256 k-elems bf16)
#define A_STG (BB*ROWB)          // 32768
#define W_STG (CPC*ROWB)         // 16384
#define W_TOT (NKB*W_STG)        // 131072 (persistent in smem)
#define DSM_BYTES (W_TOT + PIPE*A_STG)   // 229376

// Global scratch (pre-swizzled tiled layouts; chunk16 index XOR (row&7))
__device__ __align__(128) unsigned char g_W2[(size_t)NCTA * W_TOT];   // 8MB
__device__ __align__(128) unsigned char g_e2[2][NKB * A_STG];         // 2x256KB
__device__ float g_Sf[NCTA][BB];     // final-step partials only
__device__ unsigned g_flags[NCTA];   // grid barrier flags

// ---- setup: W_rec -> g_W2 (bf16 tiled+swizzled); h0 -> g_e2[1]; reset flags ----
__global__ void k_setup(const float* __restrict__ W, const float* __restrict__ h0) {
    const int tid = threadIdx.x;
    if (blockIdx.y < NKB) {
        __shared__ float s[256][33];
        const int cta = blockIdx.x, kb = blockIdx.y;
        const int n0 = cta * 32, k0 = kb * 256;
        for (int idx = tid; idx < 256 * 32; idx += TPB) {
            int k = idx >> 5, nl = idx & 31;
            s[k][nl] = W[(size_t)(k0 + k) * NN + n0 + nl];
        }
        __syncthreads();
        unsigned char* dst = g_W2 + (size_t)cta * W_TOT + (size_t)kb * W_STG;
        for (int it = tid; it < 32 * 32; it += TPB) {
            int rl = it >> 5, ch = it & 31;
            __nv_bfloat16 v[8];
#pragma unroll
            for (int j = 0; j < 8; j++) v[j] = __float2bfloat16(s[ch * 8 + j][rl]);
            *(uint4*)(dst + rl * ROWB + ((ch ^ (rl & 7)) << 4)) = *(uint4*)v;
        }
    } else {
        int item = blockIdx.x * TPB + tid;         // 64*256 = BB*NN/8
        {
            int b = item >> 8, ch = item & 255;
            __nv_bfloat16 v[8];
            const float* src = h0 + (size_t)b * NN + ch * 8;
#pragma unroll
            for (int j = 0; j < 8; j++) v[j] = __float2bfloat16(src[j]);
            int kb = ch >> 5, chl = ch & 31;
            unsigned char* dst = g_e2[1] + (size_t)kb * A_STG + b * ROWB + ((chl ^ (b & 7)) << 4);
            *(uint4*)dst = *(uint4*)v;
        }
        if (item < NCTA) g_flags[item] = 0u;
    }
}

__device__ __forceinline__ void mbar_init(unsigned mb, unsigned cnt) {
    asm volatile("mbarrier.init.shared.b64 [%0], %1;" :: "r"(mb), "r"(cnt) : "memory");
}
__device__ __forceinline__ void mbar_expect(unsigned mb, unsigned bytes) {
    asm volatile("mbarrier.arrive.expect_tx.shared.b64 _, [%0], %1;" :: "r"(mb), "r"(bytes) : "memory");
}
__device__ __forceinline__ void bulk_ld(unsigned dst, const void* src, unsigned bytes, unsigned mb) {
    asm volatile("cp.async.bulk.shared::cluster.global.mbarrier::complete_tx::bytes [%0], [%1], %2, [%3];"
                 :: "r"(dst), "l"(src), "r"(bytes), "r"(mb) : "memory");
}
__device__ __forceinline__ void mbar_wait(unsigned mb, unsigned ph) {
    asm volatile("{\n\t.reg .pred P;\n"
                 "W0_%=:\n\t"
                 "mbarrier.try_wait.parity.acquire.cta.shared::cta.b64 P, [%0], %1, 0x989680;\n\t"
                 "@P bra W1_%=;\n\t"
                 "bra W0_%=;\n"
                 "W1_%=:\n\t}"
                 :: "r"(mb), "r"(ph) : "memory");
}

__device__ __forceinline__ void grid_bar(int tid, unsigned tgt) {
    __syncthreads();
    if (tid == 0)
        asm volatile("st.release.gpu.u32 [%0], %1;" :: "l"(&g_flags[blockIdx.x]), "r"(tgt) : "memory");
    if (tid < NCTA) {
        unsigned v;
        do {
            asm volatile("ld.acquire.gpu.u32 %0, [%1];" : "=r"(v) : "l"(&g_flags[tid]) : "memory");
        } while (v < tgt);
    }
    __syncthreads();
}

#define ADV(s, p) do { if (++(s) == PIPE) { (s) = 0; (p) ^= 1; } } while (0)

extern __shared__ __align__(128) unsigned char dsm[];  // [W 128KB][A 3x32KB]

__global__ void __launch_bounds__(TPB, 1) k_step(
    const float* __restrict__ vel, const float* __restrict__ Wlin,
    const float* __restrict__ blin, float* __restrict__ out)
{
    __shared__ float sWp[2][BB], sFin[BB];
    __shared__ __align__(8) unsigned long long mbar[PIPE + 1];   // [0..2]=A stages, [3]=W

    const int tid = threadIdx.x;
    const int w = tid >> 5, l = tid & 31;
    const int g = l >> 2, tg = l & 3;
    const int mrow0 = (w & 3) * 16;
    const int nloc0 = (w >> 2) * 16;
    const int ccol0 = blockIdx.x * CPC;
    const int r0 = mrow0 + g, r1 = r0 + 8;
    const int wg = w >> 2;

    const unsigned smemW = (unsigned)__cvta_generic_to_shared(dsm);
    const unsigned smemA = smemW + W_TOT;
    unsigned mb[PIPE + 1];
#pragma unroll
    for (int p = 0; p < PIPE + 1; p++) mb[p] = (unsigned)__cvta_generic_to_shared(&mbar[p]);
    if (tid == 0) {
#pragma unroll
        for (int p = 0; p < PIPE + 1; p++) mbar_init(mb[p], 1u);
    }
    __syncthreads();

    // load persistent W slice (128KB) once
    if (tid == 0) {
        mbar_expect(mb[PIPE], W_TOT);
        bulk_ld(smemW, g_W2 + (size_t)blockIdx.x * W_TOT, W_TOT, mb[PIPE]);
    }

    // per-thread output columns + linear-layer constants
    float wl0[4], wl1[4], bl4[4]; int ncg[4];
#pragma unroll
    for (int j = 0; j < 2; j++)
#pragma unroll
        for (int q = 0; q < 2; q++) {
            int idx = j * 2 + q;
            int n = ccol0 + nloc0 + j * 8 + tg * 2 + q;
            ncg[idx] = n; wl0[idx] = Wlin[n * 2]; wl1[idx] = Wlin[n * 2 + 1]; bl4[idx] = blin[n];
        }

    // ldmatrix per-lane row bases + swizzle params
    const int rowA = mrow0 + (l & 15);
    const int mA = rowA & 7, halfA = (l >> 4) & 1;
    const unsigned aRow = smemA + rowA * ROWB;
    const int bq = l >> 3;
    const int rowB = nloc0 + ((bq & 2) ? 8 : 0) + (l & 7);
    const int mB = rowB & 7, halfB = bq & 1;
    const unsigned bRow = smemW + rowB * ROWB;

    const unsigned bAux = ((l >> 2) == 0) ? 0x3F803F80u : 0u;   // ones in col 0

    float acc[2][4];
#pragma unroll
    for (int j = 0; j < 2; j++)
#pragma unroll
        for (int q = 0; q < 4; q++) acc[j][q] = 0.f;
    float sA0 = 0.f, sA2 = 0.f, sB0 = 0.f, sB2 = 0.f;   // split aux accumulators
    float ek[8];

    mbar_wait(mb[PIPE], 0u);   // W ready
    __syncthreads();

    int cs = 0, cph = 0;   // A-pipeline cursor (slot, phase)

    for (int t = 0; t < SS; t++) {
        const unsigned char* eBuf = g_e2[(t + 1) & 1];

        // prologue: issue PIPE A-stages immediately
        if (tid == 0) {
            int s2 = cs;
#pragma unroll
            for (int i = 0; i < PIPE; i++) {
                mbar_expect(mb[s2], A_STG);
                bulk_ld(smemA + s2 * A_STG, eBuf + (size_t)i * A_STG, A_STG, mb[s2]);
                s2 = (s2 + 1 == PIPE) ? 0 : s2 + 1;
            }
        }
        // per-thread velocity prefetch (consumed in epilogue; latency hidden by GEMM)
        const float2 vr0 = __ldg((const float2*)&vel[((size_t)r0 * SS + t) * 2]);
        const float2 vr1 = __ldg((const float2*)&vel[((size_t)r1 * SS + t) * 2]);

        // ---- GEMM: 8 K-stages; A via 3-stage TMA pipeline, W persistent ----
#pragma unroll 1
        for (int kb = 0; kb < NKB; kb++) {
            const int slot = cs;
            mbar_wait(mb[slot], (unsigned)cph);
            const unsigned aB = aRow + slot * A_STG;
            const unsigned bB = bRow + kb * W_STG;
#pragma unroll
            for (int kkIdx = 0; kkIdx < KBLK / 16; kkIdx++) {
                unsigned a0, a1, a2, a3, b0, b1, b2, b3;
                unsigned aA = aB + ((unsigned)((kkIdx * 2 + halfA) ^ mA) << 4);
                unsigned bA = bB + ((unsigned)((kkIdx * 2 + halfB) ^ mB) << 4);
                asm volatile("ldmatrix.sync.aligned.m8n8.x4.shared.b16 {%0,%1,%2,%3},[%4];"
                             : "=r"(a0), "=r"(a1), "=r"(a2), "=r"(a3) : "r"(aA));
                asm volatile("ldmatrix.sync.aligned.m8n8.x4.shared.b16 {%0,%1,%2,%3},[%4];"
                             : "=r"(b0), "=r"(b1), "=r"(b2), "=r"(b3) : "r"(bA));
                asm volatile("mma.sync.aligned.m16n8k16.row.col.f32.bf16.bf16.f32 "
                             "{%0,%1,%2,%3},{%4,%5,%6,%7},{%8,%9},{%0,%1,%2,%3};"
                             : "+f"(acc[0][0]), "+f"(acc[0][1]), "+f"(acc[0][2]), "+f"(acc[0][3])
                             : "r"(a0), "r"(a1), "r"(a2), "r"(a3), "r"(b0), "r"(b1));
                asm volatile("mma.sync.aligned.m16n8k16.row.col.f32.bf16.bf16.f32 "
                             "{%0,%1,%2,%3},{%4,%5,%6,%7},{%8,%9},{%0,%1,%2,%3};"
                             : "+f"(acc[1][0]), "+f"(acc[1][1]), "+f"(acc[1][2]), "+f"(acc[1][3])
                             : "r"(a0), "r"(a1), "r"(a2), "r"(a3), "r"(b2), "r"(b3));
                // aux row-sum MMA (validated R7): split halves across warp groups,
                // alternate 2 accumulator pairs to keep the dependency chain short
                if ((wg == 0) == (kkIdx < 8)) {
                    float d1, d3;
                    if (kkIdx & 1) {
                        asm volatile("mma.sync.aligned.m16n8k16.row.col.f32.bf16.bf16.f32 "
                                     "{%0,%1,%2,%3},{%4,%5,%6,%7},{%8,%9},{%0,%1,%2,%3};"
                                     : "+f"(sB0), "+f"(d1), "+f"(sB2), "+f"(d3)
                                     : "r"(a0), "r"(a1), "r"(a2), "r"(a3), "r"(bAux), "r"(bAux));
                    } else {
                        asm volatile("mma.sync.aligned.m16n8k16.row.col.f32.bf16.bf16.f32 "
                                     "{%0,%1,%2,%3},{%4,%5,%6,%7},{%8,%9},{%0,%1,%2,%3};"
                                     : "+f"(sA0), "+f"(d1), "+f"(sA2), "+f"(d3)
                                     : "r"(a0), "r"(a1), "r"(a2), "r"(a3), "r"(bAux), "r"(bAux));
                    }
                }
            }
            __syncthreads();   // all warps done with this A slot
            if (kb + PIPE < NKB && tid == 0) {
                mbar_expect(mb[slot], A_STG);
                bulk_ld(smemA + slot * A_STG, eBuf + (size_t)(kb + PIPE) * A_STG, A_STG, mb[slot]);
            }
            ADV(cs, cph);
        }

        // ---- epilogue: s_{t-1} from aux sums; write h_{t-1}; compute e_t ----
        if (tg == 0) { sWp[wg][r0] = sA0 + sB0; sWp[wg][r1] = sA2 + sB2; }
        __syncthreads();
        const float is0 = (t == 0) ? 1.f : 1.f / (sWp[0][r0] + sWp[1][r0]);
        const float is1 = (t == 0) ? 1.f : 1.f / (sWp[0][r1] + sWp[1][r1]);

        if (t > 0) {   // write h_{t-1} = e_{t-1} / s_{t-1}
#pragma unroll
            for (int j = 0; j < 2; j++) {
                *(float2*)&out[((size_t)r0 * SS + (t - 1)) * NN + ncg[j * 2]] =
                    make_float2(ek[j * 2] * is0, ek[j * 2 + 1] * is0);
                *(float2*)&out[((size_t)r1 * SS + (t - 1)) * NN + ncg[j * 2]] =
                    make_float2(ek[4 + j * 2] * is1, ek[4 + j * 2 + 1] * is1);
            }
        }
#pragma unroll
        for (int j = 0; j < 2; j++)
#pragma unroll
            for (int q = 0; q < 2; q++) {
                int idx = j * 2 + q;
                float lin0 = fmaf(vr0.x, wl0[idx], fmaf(vr0.y, wl1[idx], bl4[idx]));
                float lin1 = fmaf(vr1.x, wl0[idx], fmaf(vr1.y, wl1[idx], bl4[idx]));
                float e0 = __expf(fmaf(acc[j][q],     is0, lin0));
                float e1 = __expf(fmaf(acc[j][2 + q], is1, lin1));
                ek[idx] = e0; ek[4 + idx] = e1;
                acc[j][q] = 0.f; acc[j][2 + q] = 0.f;
            }
        sA0 = 0.f; sA2 = 0.f; sB0 = 0.f; sB2 = 0.f;

        // store e_t into tiled+swizzled layout for next step's bulk loads
        unsigned char* ecur = g_e2[t & 1];
#pragma unroll
        for (int j = 0; j < 2; j++) {
            int n = ncg[j * 2];
            int kb2 = n >> 8, cb = (n & 255) * 2;
            unsigned sw0 = (unsigned)(((cb >> 4) ^ (r0 & 7)) << 4) | (cb & 15);
            unsigned sw1 = (unsigned)(((cb >> 4) ^ (r1 & 7)) << 4) | (cb & 15);
            *(__nv_bfloat162*)(ecur + (size_t)kb2 * A_STG + r0 * ROWB + sw0) =
                __floats2bfloat162_rn(ek[j * 2], ek[j * 2 + 1]);
            *(__nv_bfloat162*)(ecur + (size_t)kb2 * A_STG + r1 * ROWB + sw1) =
                __floats2bfloat162_rn(ek[4 + j * 2], ek[4 + j * 2 + 1]);
        }

        grid_bar(tid, (unsigned)(t + 1));
    }

    // ---- final: s_{SS-1} via one-time cross-CTA reduction, write h_{SS-1} ----
    {
        float se0 = ek[0] + ek[1] + ek[2] + ek[3];
        float se1 = ek[4] + ek[5] + ek[6] + ek[7];
        se0 += __shfl_xor_sync(0xffffffffu, se0, 1); se0 += __shfl_xor_sync(0xffffffffu, se0, 2);
        se1 += __shfl_xor_sync(0xffffffffu, se1, 1); se1 += __shfl_xor_sync(0xffffffffu, se1, 2);
        if (tg == 0) { sWp[wg][r0] = se0; sWp[wg][r1] = se1; }
        __syncthreads();
        if (tid < BB) {
            float s = sWp[0][tid] + sWp[1][tid];
            asm volatile("st.release.gpu.f32 [%0], %1;" :: "l"(&g_Sf[blockIdx.x][tid]), "f"(s) : "memory");
        }
        grid_bar(tid, (unsigned)(SS + 1));
        if (tid < BB) {
            const float* pp = &g_Sf[0][0] + tid;
            float a0=0,a1=0,a2=0,a3=0,a4=0,a5=0,a6=0,a7=0;
#pragma unroll
            for (int c = 0; c < NCTA; c += 8) {
                a0 += __ldcg(pp + (c+0)*BB); a1 += __ldcg(pp + (c+1)*BB);
                a2 += __ldcg(pp + (c+2)*BB); a3 += __ldcg(pp + (c+3)*BB);
                a4 += __ldcg(pp + (c+4)*BB); a5 += __ldcg(pp + (c+5)*BB);
                a6 += __ldcg(pp + (c+6)*BB); a7 += __ldcg(pp + (c+7)*BB);
            }
            sFin[tid] = (((a0+a1)+(a2+a3)) + ((a4+a5)+(a6+a7)));
        }
        __syncthreads();
        const float is0 = 1.f / sFin[r0], is1 = 1.f / sFin[r1];
#pragma unroll
        for (int j = 0; j < 2; j++) {
            *(float2*)&out[((size_t)r0 * SS + (SS - 1)) * NN + ncg[j * 2]] =
                make_float2(ek[j * 2] * is0, ek[j * 2 + 1] * is0);
            *(float2*)&out[((size_t)r1 * SS + (SS - 1)) * NN + ncg[j * 2]] =
                make_float2(ek[4 + j * 2] * is1, ek[4 + j * 2 + 1] * is1);
        }
    }
}

extern "C" void kernel_launch(void* const* d_in, const int* in_sizes, int n_in,
                              void* d_out, int out_size) {
    const float* vel  = (const float*)d_in[0];
    const float* h0   = (const float*)d_in[1];
    const float* Wlin = (const float*)d_in[2];
    const float* blin = (const float*)d_in[3];
    const float* Wrec = (const float*)d_in[4];
    float* out = (float*)d_out;
    static int configured = 0;
    if (!configured) {
        cudaFuncSetAttribute(k_step, cudaFuncAttributeMaxDynamicSharedMemorySize, DSM_BYTES);
        configured = 1;
    }
    k_setup<<<dim3(NCTA, NKB + 1), TPB>>>(Wrec, h0);
    k_step<<<NCTA, TPB, DSM_BYTES>>>(vel, Wlin, blin, out);
}